// round 7
// baseline (speedup 1.0000x reference)
#include <cuda_runtime.h>
#include <math.h>

#define Bdim 256
#define Jdim 64
#define Ddim 512
#define SST 516      // s tile row stride (floats): 516 % 32 == 4 -> conflict-free A loads
#define UST 516      // U slab row stride (uint2):  516 % 16 == 4 -> conflict-free LDS.64

// Scratch (allocation-free rule: __device__ globals)
__device__ float g_Q[Bdim * Ddim];     // inputs @ W
__device__ float g_P[Jdim * Ddim];     // keys @ V + U_bias
__device__ uint2 g_U2[Ddim * Ddim];    // U pre-split: (tf32_hi, tf32_lo) per element

// ---------------- cp.async helpers ----------------
__device__ __forceinline__ void cp_async16(void* smem_dst, const void* gmem_src) {
    unsigned s = (unsigned)__cvta_generic_to_shared(smem_dst);
    asm volatile("cp.async.cg.shared.global [%0], [%1], 16;\n" :: "r"(s), "l"(gmem_src));
}
__device__ __forceinline__ void cp_commit() { asm volatile("cp.async.commit_group;\n"); }
__device__ __forceinline__ void cp_wait1()  { asm volatile("cp.async.wait_group 1;\n"); }
__device__ __forceinline__ void cp_wait0()  { asm volatile("cp.async.wait_group 0;\n"); }

// ---------------- tf32 helpers ----------------
__device__ __forceinline__ unsigned f2tf32(float x) {
    unsigned r;
    asm("cvt.rna.tf32.f32 %0, %1;" : "=r"(r) : "f"(x));
    return r;
}
__device__ __forceinline__ void split_tf32(float x, unsigned& hi, unsigned& lo) {
    hi = f2tf32(x);
    float h = __uint_as_float(hi);
    lo = f2tf32(x - h);
}
// D += A(16x8,row) * B(8x8,col)   (tf32 in, fp32 acc)
__device__ __forceinline__ void mma_tf32(float d[4], const unsigned a[4], const unsigned b[2]) {
    asm volatile("mma.sync.aligned.m16n8k8.row.col.f32.tf32.tf32.f32 "
        "{%0,%1,%2,%3}, {%4,%5,%6,%7}, {%8,%9}, {%0,%1,%2,%3};"
        : "+f"(d[0]), "+f"(d[1]), "+f"(d[2]), "+f"(d[3])
        : "r"(a[0]), "r"(a[1]), "r"(a[2]), "r"(a[3]), "r"(b[0]), "r"(b[1]));
}

// ---------------- precompute: Q = inputs@W ; P = keys@V + bias ; split(U) ----------------
__device__ __forceinline__ void sgemm_tile_body(
    const float* __restrict__ A, const float* __restrict__ Bm,
    const float* __restrict__ bias, float* __restrict__ C,
    int m0, int n0, int N, int K,
    float (*As)[64], float (*Bs)[64])
{
    int tid = threadIdx.x;
    int ty = tid >> 4, tx = tid & 15;
    float acc[4][4];
#pragma unroll
    for (int i = 0; i < 4; i++)
#pragma unroll
        for (int j = 0; j < 4; j++) acc[i][j] = 0.f;

    for (int k0 = 0; k0 < K; k0 += 16) {
        {
            int m  = tid >> 2;
            int kk = (tid & 3) * 4;
            float4 v = *reinterpret_cast<const float4*>(&A[(size_t)(m0 + m) * K + k0 + kk]);
            As[kk + 0][m] = v.x; As[kk + 1][m] = v.y;
            As[kk + 2][m] = v.z; As[kk + 3][m] = v.w;
        }
        {
            int kk = tid >> 4;
            int c4 = (tid & 15) * 4;
            *reinterpret_cast<float4*>(&Bs[kk][c4]) =
                *reinterpret_cast<const float4*>(&Bm[(size_t)(k0 + kk) * N + n0 + c4]);
        }
        __syncthreads();
#pragma unroll
        for (int kk = 0; kk < 16; kk++) {
            float4 a4 = *reinterpret_cast<const float4*>(&As[kk][ty * 4]);
            float4 b4 = *reinterpret_cast<const float4*>(&Bs[kk][tx * 4]);
            float a[4] = {a4.x, a4.y, a4.z, a4.w};
            float b[4] = {b4.x, b4.y, b4.z, b4.w};
#pragma unroll
            for (int i = 0; i < 4; i++)
#pragma unroll
                for (int j = 0; j < 4; j++) acc[i][j] += a[i] * b[j];
        }
        __syncthreads();
    }
    float bx = 0.f, by = 0.f, bz = 0.f, bw = 0.f;
    if (bias) {
        bx = bias[n0 + tx * 4 + 0]; by = bias[n0 + tx * 4 + 1];
        bz = bias[n0 + tx * 4 + 2]; bw = bias[n0 + tx * 4 + 3];
    }
#pragma unroll
    for (int i = 0; i < 4; i++) {
        float4 o;
        o.x = acc[i][0] + bx; o.y = acc[i][1] + by;
        o.z = acc[i][2] + bz; o.w = acc[i][3] + bw;
        *reinterpret_cast<float4*>(&C[(size_t)(m0 + ty * 4 + i) * N + n0 + tx * 4]) = o;
    }
}

__global__ __launch_bounds__(256) void precompute_kernel(
    const float* __restrict__ inputs, const float* __restrict__ keys,
    const float* __restrict__ V, const float* __restrict__ W,
    const float* __restrict__ U, const float* __restrict__ Ubias)
{
    __shared__ float As[16][64];
    __shared__ float Bs[16][64];
    int bx = blockIdx.x;
    if (bx < 32) {
        sgemm_tile_body(inputs, W, nullptr, g_Q,
                        (bx >> 3) * 64, (bx & 7) * 64, Ddim, Ddim, As, Bs);
    } else if (bx < 40) {
        int t = bx - 32;
        sgemm_tile_body(keys, V, Ubias, g_P,
                        0, t * 64, Ddim, Ddim, As, Bs);
    } else {
        // split U into (hi, lo) tf32 pairs: 64 blocks x 256 threads x 16 elems
        int t = bx - 40;
        int base = t * 4096 + threadIdx.x * 16;
#pragma unroll
        for (int q = 0; q < 4; q++) {
            int i = base + q * 4;
            float4 u = *reinterpret_cast<const float4*>(&U[i]);
            uint2 o0, o1, o2, o3;
            split_tf32(u.x, o0.x, o0.y);
            split_tf32(u.y, o1.x, o1.y);
            split_tf32(u.z, o2.x, o2.y);
            split_tf32(u.w, o3.x, o3.y);
            uint4* dst = reinterpret_cast<uint4*>(&g_U2[i]);
            dst[0] = make_uint4(o0.x, o0.y, o1.x, o1.y);
            dst[1] = make_uint4(o2.x, o2.y, o3.x, o3.y);
        }
    }
}

// ---------------- fused main kernel ----------------
// CTA = one batch element b: 64 rows (all j) x 512 cols. 512 threads, 16 warps
// arranged 2 (row groups of 32) x 8 (col groups of 64). Warp tile 32x64.
__global__ __launch_bounds__(512, 1) void fused_kernel(
    const float* __restrict__ inputs,
    const float* __restrict__ state,
    const float* __restrict__ keys,
    float* __restrict__ out)
{
    extern __shared__ char smraw[];
    float* s_sm   = reinterpret_cast<float*>(smraw);                    // [64][SST]
    uint2* Ubuf2  = reinterpret_cast<uint2*>(smraw + 64 * SST * 4);     // 2 x [8][UST]
    float* inp    = reinterpret_cast<float*>(smraw + 64 * SST * 4 + 2 * 8 * UST * 8);
    float* qb     = inp + Ddim;
    float* gate   = qb + Ddim;        // [64]
    float* normv  = gate + 64;        // [64]
    float* red    = normv + 64;       // [8][64]

    int tid  = threadIdx.x;
    int bx   = blockIdx.x;            // = b
    int row0 = bx * 64;
    const float* srow = state + (size_t)row0 * Ddim;

    int lane = tid & 31;
    int w    = tid >> 5;              // 0..15
    int wcol = w & 7;
    int wrow = w >> 3;
    int gid  = lane >> 2;             // 0..7
    int tig  = lane & 3;              // 0..3
    int cb   = wcol * 64;             // warp column base
    int rb   = wrow * 32;             // warp row base

    // Prefetch U2 slabs 0 and 1 (each 8 x 512 uint2 = 32KB)
#pragma unroll
    for (int q = 0; q < 4; q++) {
        int c = tid + 512 * q;
        int kk = c >> 8, off = (c & 255) * 2;
        cp_async16(Ubuf2 + kk * UST + off, g_U2 + (size_t)kk * Ddim + off);
    }
    cp_commit();
#pragma unroll
    for (int q = 0; q < 4; q++) {
        int c = tid + 512 * q;
        int kk = c >> 8, off = (c & 255) * 2;
        cp_async16(Ubuf2 + 8 * UST + kk * UST + off, g_U2 + (size_t)(8 + kk) * Ddim + off);
    }
    cp_commit();

    // Stage inputs[b] and Q[b]
    if (tid < 128)
        reinterpret_cast<float4*>(inp)[tid] =
            reinterpret_cast<const float4*>(inputs + (size_t)bx * Ddim)[tid];
    else if (tid < 256)
        reinterpret_cast<float4*>(qb)[tid - 128] =
            reinterpret_cast<const float4*>(g_Q + (size_t)bx * Ddim)[tid - 128];

    // Stage s block [64][512] -> padded [64][SST]
#pragma unroll
    for (int q = 0; q < 16; q++) {
        int c = tid + 512 * q;
        int r = c >> 7;
        int f4 = c & 127;
        float4 v = reinterpret_cast<const float4*>(srow + (size_t)r * Ddim)[f4];
        *reinterpret_cast<float4*>(&s_sm[r * SST + f4 * 4]) = v;
    }
    __syncthreads();

    // Gates: warp w -> rows w*4..w*4+3 ; arg = inputs.(s_j + key_j)
#pragma unroll
    for (int i = 0; i < 4; i++) {
        int r = w * 4 + i;                         // r == j (CTA spans all j of one b)
        const float* kr = keys + (size_t)r * Ddim;
        const float* sr = s_sm + r * SST;
        float z = 0.f;
        for (int k = lane; k < Ddim; k += 32)
            z += inp[k] * (sr[k] + kr[k]);
#pragma unroll
        for (int o = 16; o; o >>= 1) z += __shfl_xor_sync(0xffffffffu, z, o);
        if (lane == 0) gate[r] = 1.f / (1.f + expf(-z));
    }

    // -------- tf32 split-3 MMA mainloop --------
    float acc[2][8][4];
#pragma unroll
    for (int mi = 0; mi < 2; mi++)
#pragma unroll
        for (int nf = 0; nf < 8; nf++)
#pragma unroll
            for (int c = 0; c < 4; c++) acc[mi][nf][c] = 0.f;

#pragma unroll 1
    for (int s = 0; s < 64; s++) {
        if (s < 62) cp_wait1(); else cp_wait0();
        __syncthreads();
        const uint2* Ub = Ubuf2 + (s & 1) * (8 * UST);
        int k0 = s * 8;

        // A fragments: rows rb + mi*16 + {gid, gid+8}, cols k0 + {tig, tig+4}; split hi/lo
        unsigned ah[2][4], al[2][4];
#pragma unroll
        for (int mi = 0; mi < 2; mi++) {
            const float* Sb = s_sm + (rb + mi * 16 + gid) * SST + k0 + tig;
            float f0 = Sb[0];
            float f1 = Sb[8 * SST];
            float f2 = Sb[4];
            float f3 = Sb[8 * SST + 4];
            split_tf32(f0, ah[mi][0], al[mi][0]);
            split_tf32(f1, ah[mi][1], al[mi][1]);
            split_tf32(f2, ah[mi][2], al[mi][2]);
            split_tf32(f3, ah[mi][3], al[mi][3]);
        }

#pragma unroll
        for (int nf = 0; nf < 8; nf++) {
            int col = cb + nf * 8 + gid;
            uint2 e0 = Ub[tig * UST + col];          // (hi, lo) @ k = tig
            uint2 e1 = Ub[(tig + 4) * UST + col];    // (hi, lo) @ k = tig+4
            unsigned bh[2] = {e0.x, e1.x};
            unsigned bl[2] = {e0.y, e1.y};
#pragma unroll
            for (int mi = 0; mi < 2; mi++) {
                mma_tf32(acc[mi][nf], ah[mi], bh);
                mma_tf32(acc[mi][nf], al[mi], bh);
                mma_tf32(acc[mi][nf], ah[mi], bl);
            }
        }
        __syncthreads();
        if (s + 2 < 64) {
            const uint2* Ug = g_U2 + (size_t)(s + 2) * 8 * Ddim;
            uint2* Ud = Ubuf2 + (s & 1) * (8 * UST);
#pragma unroll
            for (int q = 0; q < 4; q++) {
                int c = tid + 512 * q;
                int kk = c >> 8, off = (c & 255) * 2;
                cp_async16(Ud + kk * UST + off, Ug + (size_t)kk * Ddim + off);
            }
            cp_commit();
        }
    }

    // -------- epilogue: v = s + g*relu(acc + qb + P), row-norm partials --------
    float part[4];
#pragma unroll
    for (int mi = 0; mi < 2; mi++) {
#pragma unroll
        for (int h = 0; h < 2; h++) {
            int r = rb + mi * 16 + h * 8 + gid;     // 0..63; r == j
            float g = gate[r];
            const float* Pr = g_P + (size_t)r * Ddim;
            const float* Sr = s_sm + r * SST;
            float psum = 0.f;
#pragma unroll
            for (int nf = 0; nf < 8; nf++) {
                int c0 = cb + nf * 8 + tig * 2;
                float2 p2 = *reinterpret_cast<const float2*>(Pr + c0);
                float2 s2 = *reinterpret_cast<const float2*>(Sr + c0);
                float pre0 = acc[mi][nf][h * 2 + 0] + qb[c0]     + p2.x;
                float pre1 = acc[mi][nf][h * 2 + 1] + qb[c0 + 1] + p2.y;
                float v0 = s2.x + g * fmaxf(pre0, 0.f);
                float v1 = s2.y + g * fmaxf(pre1, 0.f);
                acc[mi][nf][h * 2 + 0] = v0;
                acc[mi][nf][h * 2 + 1] = v1;
                psum += v0 * v0 + v1 * v1;
            }
            part[mi * 2 + h] = psum;
        }
    }
#pragma unroll
    for (int i = 0; i < 4; i++) {
        part[i] += __shfl_xor_sync(0xffffffffu, part[i], 1);
        part[i] += __shfl_xor_sync(0xffffffffu, part[i], 2);
    }
    if (tig == 0) {
#pragma unroll
        for (int mi = 0; mi < 2; mi++)
#pragma unroll
            for (int h = 0; h < 2; h++)
                red[wcol * 64 + rb + mi * 16 + h * 8 + gid] = part[mi * 2 + h];
    }
    __syncthreads();
    if (tid < 64) {
        float sum = 0.f;
#pragma unroll
        for (int ww = 0; ww < 8; ww++) sum += red[ww * 64 + tid];
        normv[tid] = fmaxf(sqrtf(sum), 1e-12f);
    }
    __syncthreads();

    // out = (v > 0) ? norm : v
#pragma unroll
    for (int mi = 0; mi < 2; mi++) {
#pragma unroll
        for (int h = 0; h < 2; h++) {
            int r = rb + mi * 16 + h * 8 + gid;
            float n = normv[r];
            float* orow = out + (size_t)(row0 + r) * Ddim;
#pragma unroll
            for (int nf = 0; nf < 8; nf++) {
                int c0 = cb + nf * 8 + tig * 2;
                float v0 = acc[mi][nf][h * 2 + 0];
                float v1 = acc[mi][nf][h * 2 + 1];
                float2 o;
                o.x = v0 > 0.f ? n : v0;
                o.y = v1 > 0.f ? n : v1;
                *reinterpret_cast<float2*>(orow + c0) = o;
            }
        }
    }
}

extern "C" void kernel_launch(void* const* d_in, const int* in_sizes, int n_in,
                              void* d_out, int out_size)
{
    const float* inputs = (const float*)d_in[0];
    const float* state  = (const float*)d_in[1];
    const float* keys   = (const float*)d_in[2];
    const float* U      = (const float*)d_in[3];
    const float* V      = (const float*)d_in[4];
    const float* W      = (const float*)d_in[5];
    const float* Ubias  = (const float*)d_in[6];
    float* out = (float*)d_out;
    (void)in_sizes; (void)n_in; (void)out_size;

    // Q = inputs@W (32 blks), P = keys@V + bias (8 blks), U split (64 blks)
    precompute_kernel<<<104, 256>>>(inputs, keys, V, W, U, Ubias);

    size_t smem = (size_t)64 * SST * 4          // s tile
                + (size_t)2 * 8 * UST * 8       // U2 double buffer
                + (Ddim + Ddim + 64 + 64 + 8 * 64) * 4;
    cudaFuncSetAttribute(fused_kernel, cudaFuncAttributeMaxDynamicSharedMemorySize, (int)smem);
    fused_kernel<<<Bdim, 512, smem>>>(inputs, state, keys, out);
}